// round 4
// baseline (speedup 1.0000x reference)
#include <cuda_runtime.h>
#include <cuda_bf16.h>
#include <math.h>

// Problem constants
#define FIN    64
#define CH     128          // C
#define STEPS  4
#define NMAX   100096       // 100000 padded up to multiple of 128
#define NEMAX  1600000
#define GW     512          // GRU GEMM output width (4*C)

// ---------------- scratch (static device allocations; no cudaMalloc) ------
__device__ float g_h   [(size_t)NMAX * CH];     // node hidden state
__device__ float g_m   [(size_t)NMAX * CH];     // mpnn message
__device__ float g_agg [(size_t)NMAX * CH];     // scatter-add target
__device__ float g_G   [(size_t)NMAX * GW];     // GRU GEMM output
__device__ float g_Wall[256 * GW];              // combined GRU weights (B layout [K=256, N=512])
__device__ float g_WinT[FIN * CH];              // W_in transposed -> [K=64, N=128]
__device__ float g_gsum[CH];                    // readout partial sums
__device__ int   g_sd  [2 * NEMAX];             // normalized int32 [src | dst]
__device__ int   g_idx64;                       // 1 if edge_index buffer is int64

// ---------------- edge-index dtype detection / normalization ---------------
// If the buffer holds int64 values < 2^31 (node ids < 100000), every odd
// 32-bit word is zero.  If it holds int32 random ids, the odd words are
// nonzero with overwhelming probability.  Deterministic per input.
__global__ void detect_idx_kernel(const int* __restrict__ w, int* __restrict__ flag)
{
    __shared__ int s_any;
    if (threadIdx.x == 0) s_any = 0;
    __syncthreads();
    int v = w[2 * threadIdx.x + 1];              // odd words 1,3,...,1023
    if (v != 0) atomicOr(&s_any, 1);
    __syncthreads();
    if (threadIdx.x == 0) *flag = (s_any == 0) ? 1 : 0;   // all-zero -> int64
}

__global__ void convert_idx_kernel(const void* __restrict__ ei,
                                   int* __restrict__ sd,
                                   const int* __restrict__ flag, int total)
{
    int i = blockIdx.x * blockDim.x + threadIdx.x;
    if (i >= total) return;
    if (*flag) sd[i] = (int)((const long long*)ei)[i];
    else       sd[i] = ((const int*)ei)[i];
}

// ---------------- small prep kernels --------------------------------------
__global__ void prep_wint_kernel(const float* __restrict__ W_in, float* __restrict__ WinT) {
    int idx = blockIdx.x * blockDim.x + threadIdx.x;     // 64*128
    if (idx >= FIN * CH) return;
    int k = idx >> 7;        // 0..63
    int n = idx & 127;       // 0..127
    WinT[k * CH + n] = W_in[n * FIN + k];                // W_in is [C, F_IN]
}

__global__ void prep_wall_kernel(const float* __restrict__ W_ih,
                                 const float* __restrict__ W_hh,
                                 float* __restrict__ Wall) {
    int idx = blockIdx.x * blockDim.x + threadIdx.x;     // 256*512
    if (idx >= 256 * GW) return;
    int k = idx >> 9;        // 0..255
    int n = idx & 511;       // 0..511
    float v;
    if (n < 256) {
        // r,z gates: gi + gh summed.  k<128 -> agg half (W_ih), k>=128 -> h half (W_hh)
        v = (k < 128) ? W_ih[n * CH + k] : W_hh[n * CH + (k - 128)];
    } else if (n < 384) {
        // gi_n: only agg half contributes
        int j = n - 256;
        v = (k < 128) ? W_ih[(256 + j) * CH + k] : 0.0f;
    } else {
        // gh_n: only h half contributes
        int j = n - 384;
        v = (k < 128) ? 0.0f : W_hh[(256 + j) * CH + (k - 128)];
    }
    Wall[k * GW + n] = v;
}

// ---------------- generic tiled fp32 GEMM ---------------------------------
//  D[M,N] = A[M,K] @ B[K,N]    (row-major; ldb = N)
//  A split across two pointers: global k < K0 reads A0, else A1 (both lda).
#define BM 128
#define BN 128
#define BK 16
#define TM 8
#define TN 8

__global__ __launch_bounds__(256)
void gemm_kernel(const float* __restrict__ A0, const float* __restrict__ A1,
                 int K0, int lda,
                 const float* __restrict__ B, float* __restrict__ D,
                 int M, int N, int K)
{
    __shared__ float As[BK][BM];
    __shared__ float Bs[BK][BN];

    const int tid  = threadIdx.x;
    const int bn   = blockIdx.x;
    const int bm   = blockIdx.y;
    const int row0 = bm * BM;
    const int tx   = tid & 15;          // 0..15
    const int ty   = tid >> 4;          // 0..15

    float acc[TM][TN];
    #pragma unroll
    for (int i = 0; i < TM; i++)
        #pragma unroll
        for (int j = 0; j < TN; j++) acc[i][j] = 0.0f;

    for (int kt = 0; kt < K; kt += BK) {
        const float* Aptr;
        int kloc;
        if (kt < K0) { Aptr = A0; kloc = kt; }
        else         { Aptr = A1; kloc = kt - K0; }

        #pragma unroll
        for (int t = 0; t < 2; t++) {
            int id = tid + t * 256;                 // 0..511
            // ---- A tile: 128 rows x 16 k, stored transposed As[k][m]
            int arow = id >> 2;                     // 0..127
            int ak   = (id & 3) * 4;                // 0,4,8,12
            int grow = row0 + arow;
            float4 v = make_float4(0.f, 0.f, 0.f, 0.f);
            if (grow < M)
                v = *reinterpret_cast<const float4*>(Aptr + (size_t)grow * lda + kloc + ak);
            As[ak + 0][arow] = v.x;
            As[ak + 1][arow] = v.y;
            As[ak + 2][arow] = v.z;
            As[ak + 3][arow] = v.w;
            // ---- B tile: 16 k x 128 n
            int brow = id >> 5;                     // 0..15
            int bcol = (id & 31) * 4;               // 0..124
            float4 w = *reinterpret_cast<const float4*>(
                B + (size_t)(kt + brow) * N + bn * BN + bcol);
            *reinterpret_cast<float4*>(&Bs[brow][bcol]) = w;
        }
        __syncthreads();

        #pragma unroll
        for (int k = 0; k < BK; k++) {
            float4 a0 = *reinterpret_cast<const float4*>(&As[k][ty * TM]);
            float4 a1 = *reinterpret_cast<const float4*>(&As[k][ty * TM + 4]);
            float4 b0 = *reinterpret_cast<const float4*>(&Bs[k][tx * TN]);
            float4 b1 = *reinterpret_cast<const float4*>(&Bs[k][tx * TN + 4]);
            float af[TM] = {a0.x, a0.y, a0.z, a0.w, a1.x, a1.y, a1.z, a1.w};
            float bf[TN] = {b0.x, b0.y, b0.z, b0.w, b1.x, b1.y, b1.z, b1.w};
            #pragma unroll
            for (int i = 0; i < TM; i++)
                #pragma unroll
                for (int j = 0; j < TN; j++)
                    acc[i][j] += af[i] * bf[j];
        }
        __syncthreads();
    }

    #pragma unroll
    for (int i = 0; i < TM; i++) {
        int grow = row0 + ty * TM + i;
        if (grow < M) {
            float* dp = D + (size_t)grow * N + bn * BN + tx * TN;
            *reinterpret_cast<float4*>(dp)     = make_float4(acc[i][0], acc[i][1], acc[i][2], acc[i][3]);
            *reinterpret_cast<float4*>(dp + 4) = make_float4(acc[i][4], acc[i][5], acc[i][6], acc[i][7]);
        }
    }
}

// ---------------- scatter-add: one warp per edge --------------------------
__global__ __launch_bounds__(256)
void scatter_kernel(const int* __restrict__ sd,
                    const float* __restrict__ m,
                    float* __restrict__ agg, int nE)
{
    int warp = (blockIdx.x * blockDim.x + threadIdx.x) >> 5;
    int lane = threadIdx.x & 31;
    if (warp >= nE) return;
    int s = sd[warp];           // src
    int d = sd[nE + warp];      // dst
    float4 v = *reinterpret_cast<const float4*>(m + (size_t)s * CH + lane * 4);
    float* dp = agg + (size_t)d * CH + lane * 4;
    asm volatile("red.global.add.v4.f32 [%0], {%1, %2, %3, %4};"
                 :: "l"(dp), "f"(v.x), "f"(v.y), "f"(v.z), "f"(v.w)
                 : "memory");
}

// ---------------- GRU gate epilogue ---------------------------------------
__global__ void gates_kernel(const float* __restrict__ G,
                             const float* __restrict__ b_ih,
                             const float* __restrict__ b_hh,
                             float* __restrict__ h, int nN)
{
    int idx = blockIdx.x * blockDim.x + threadIdx.x;
    if (idx >= nN * CH) return;
    int n = idx >> 7;
    int c = idx & 127;
    const float* g = G + (size_t)n * GW;
    float r   = 1.0f / (1.0f + expf(-(g[c]       + b_ih[c]       + b_hh[c])));
    float z   = 1.0f / (1.0f + expf(-(g[128 + c] + b_ih[128 + c] + b_hh[128 + c])));
    float gin = g[256 + c] + b_ih[256 + c];
    float ghn = g[384 + c] + b_hh[256 + c];
    float nn  = tanhf(gin + r * ghn);
    float ho  = h[idx];
    h[idx] = (1.0f - z) * nn + z * ho;
}

// ---------------- readout --------------------------------------------------
__global__ void reduce_kernel(const float* __restrict__ h, float* __restrict__ gsum, int nN)
{
    int c = threadIdx.x;    // 128 threads/block, one channel each
    float acc = 0.0f;
    for (int n = blockIdx.x; n < nN; n += gridDim.x) {
        float v = h[(size_t)n * CH + c];
        v = (v >= 0.0f) ? v : 0.01f * v;      // LeakyReLU
        acc += v;
    }
    atomicAdd(&gsum[c], acc);
}

__global__ void final_kernel(const float* __restrict__ gsum,
                             const float* __restrict__ W_pred,
                             const float* __restrict__ b_pred,
                             float* __restrict__ out, float invN)
{
    __shared__ float s[CH];
    int t = threadIdx.x;
    s[t] = gsum[t] * invN * W_pred[t];
    __syncthreads();
    #pragma unroll
    for (int o = 64; o > 0; o >>= 1) {
        if (t < o) s[t] += s[t + o];
        __syncthreads();
    }
    if (t == 0) out[0] = s[0] + b_pred[0];
}

// ---------------- launch ----------------------------------------------------
extern "C" void kernel_launch(void* const* d_in, const int* in_sizes, int n_in,
                              void* d_out, int out_size)
{
    const float*  x      = (const float*)d_in[0];
    const void*   ei     = d_in[1];                  // int32 or int64 node ids
    const float*  W_in   = (const float*)d_in[2];
    const float*  W_mpnn = (const float*)d_in[3];
    const float*  W_ih   = (const float*)d_in[4];
    const float*  W_hh   = (const float*)d_in[5];
    const float*  b_ih   = (const float*)d_in[6];
    const float*  b_hh   = (const float*)d_in[7];
    const float*  W_pred = (const float*)d_in[8];
    const float*  b_pred = (const float*)d_in[9];
    float*        out    = (float*)d_out;
    (void)n_in; (void)out_size;

    const int nN = in_sizes[0] / FIN;      // 100000
    const int nE = in_sizes[1] / 2;        // 1600000

    float *p_h, *p_m, *p_agg, *p_G, *p_Wall, *p_WinT, *p_gsum;
    int *p_sd, *p_flag;
    cudaGetSymbolAddress((void**)&p_h,    g_h);
    cudaGetSymbolAddress((void**)&p_m,    g_m);
    cudaGetSymbolAddress((void**)&p_agg,  g_agg);
    cudaGetSymbolAddress((void**)&p_G,    g_G);
    cudaGetSymbolAddress((void**)&p_Wall, g_Wall);
    cudaGetSymbolAddress((void**)&p_WinT, g_WinT);
    cudaGetSymbolAddress((void**)&p_gsum, g_gsum);
    cudaGetSymbolAddress((void**)&p_sd,   g_sd);
    cudaGetSymbolAddress((void**)&p_flag, g_idx64);

    const int mtiles = (nN + BM - 1) / BM;

    // prep: edge-index normalization + weight repacking
    detect_idx_kernel<<<1, 512>>>((const int*)ei, p_flag);
    convert_idx_kernel<<<(2 * nE + 255) / 256, 256>>>(ei, p_sd, p_flag, 2 * nE);
    prep_wint_kernel<<<(FIN * CH + 255) / 256, 256>>>(W_in, p_WinT);
    prep_wall_kernel<<<(256 * GW + 255) / 256, 256>>>(W_ih, W_hh, p_Wall);

    // h = x @ W_in^T     [nN,64] @ [64,128]
    {
        dim3 grid(CH / BN, mtiles);
        gemm_kernel<<<grid, 256>>>(x, x, FIN, FIN, p_WinT, p_h, nN, CH, FIN);
    }

    for (int i = 0; i < STEPS; i++) {
        // m = h @ W_mpnn[i]       [nN,128] @ [128,128]
        {
            dim3 grid(CH / BN, mtiles);
            gemm_kernel<<<grid, 256>>>(p_h, p_h, CH, CH,
                                       W_mpnn + (size_t)i * CH * CH, p_m, nN, CH, CH);
        }
        // agg = scatter_add(m[src] -> dst)
        cudaMemsetAsync(p_agg, 0, (size_t)nN * CH * sizeof(float));
        {
            int warps_per_block = 256 / 32;
            int blocks = (nE + warps_per_block - 1) / warps_per_block;
            scatter_kernel<<<blocks, 256>>>(p_sd, p_m, p_agg, nE);
        }
        // G = [agg|h] @ Wall      [nN,256] @ [256,512]
        {
            dim3 grid(GW / BN, mtiles);
            gemm_kernel<<<grid, 256>>>(p_agg, p_h, CH, CH, p_Wall, p_G, nN, GW, 2 * CH);
        }
        // GRU gate update (in-place on h)
        gates_kernel<<<(nN * CH + 255) / 256, 256>>>(p_G, b_ih, b_hh, p_h, nN);
    }

    // readout: LeakyReLU -> mean -> linear
    cudaMemsetAsync(p_gsum, 0, CH * sizeof(float));
    reduce_kernel<<<2048, CH>>>(p_h, p_gsum, nN);
    final_kernel<<<1, CH>>>(p_gsum, W_pred, b_pred, out, 1.0f / (float)nN);
}

// round 5
// speedup vs baseline: 1.2970x; 1.2970x over previous
#include <cuda_runtime.h>
#include <cuda_bf16.h>
#include <math.h>

// Problem constants
#define FIN    64
#define CH     128          // C
#define STEPS  4
#define NMAX   100096       // 100000 padded up to multiple of 128
#define NEMAX  1600000
#define GW     512          // GRU GEMM output width (4*C)

// ---------------- scratch (static device allocations; no cudaMalloc) ------
__device__ float g_h   [(size_t)NMAX * CH];     // node hidden state
__device__ float g_m   [(size_t)NMAX * CH];     // mpnn message
__device__ float g_agg [(size_t)NMAX * CH];     // scatter-add target
__device__ float g_G   [(size_t)NMAX * GW];     // GRU GEMM output
__device__ float g_Wall[256 * GW];              // combined GRU weights [K=256, N=512]
__device__ float g_WinT[FIN * CH];              // W_in transposed -> [K=64, N=128]
__device__ float g_gsum[CH];                    // readout partial sums
__device__ int   g_sd  [2 * NEMAX];             // normalized int32 [src | dst]
__device__ int   g_idx64;                       // 1 if edge_index buffer is int64

// ---------------- edge-index dtype detection / normalization ---------------
__global__ void detect_idx_kernel(const int* __restrict__ w, int* __restrict__ flag)
{
    __shared__ int s_any;
    if (threadIdx.x == 0) s_any = 0;
    __syncthreads();
    int v = w[2 * threadIdx.x + 1];              // odd words 1,3,...,1023
    if (v != 0) atomicOr(&s_any, 1);
    __syncthreads();
    if (threadIdx.x == 0) *flag = (s_any == 0) ? 1 : 0;   // all-zero -> int64
}

__global__ void convert_idx_kernel(const void* __restrict__ ei,
                                   int* __restrict__ sd,
                                   const int* __restrict__ flag, int total)
{
    int i = blockIdx.x * blockDim.x + threadIdx.x;
    if (i >= total) return;
    if (*flag) sd[i] = (int)((const long long*)ei)[i];
    else       sd[i] = ((const int*)ei)[i];
}

// ---------------- small prep kernels --------------------------------------
__global__ void prep_wint_kernel(const float* __restrict__ W_in, float* __restrict__ WinT) {
    int idx = blockIdx.x * blockDim.x + threadIdx.x;     // 64*128
    if (idx >= FIN * CH) return;
    int k = idx >> 7;
    int n = idx & 127;
    WinT[k * CH + n] = W_in[n * FIN + k];                // W_in is [C, F_IN]
}

__global__ void prep_wall_kernel(const float* __restrict__ W_ih,
                                 const float* __restrict__ W_hh,
                                 float* __restrict__ Wall) {
    int idx = blockIdx.x * blockDim.x + threadIdx.x;     // 256*512
    if (idx >= 256 * GW) return;
    int k = idx >> 9;        // 0..255
    int n = idx & 511;       // 0..511
    float v;
    if (n < 256) {
        v = (k < 128) ? W_ih[n * CH + k] : W_hh[n * CH + (k - 128)];
    } else if (n < 384) {
        int j = n - 256;
        v = (k < 128) ? W_ih[(256 + j) * CH + k] : 0.0f;
    } else {
        int j = n - 384;
        v = (k < 128) ? 0.0f : W_hh[(256 + j) * CH + (k - 128)];
    }
    Wall[k * GW + n] = v;
}

// ---------------- double-buffered tiled fp32 GEMM -------------------------
//  D[M,N] = A[M,K] @ B[K,N]    (row-major; ldb = N)
//  A split across two pointers: global k < K0 reads A0, else A1 (both lda).
//  gru != 0: per-bn K-range skips structurally-zero B blocks:
//     bn==2 -> k in [0,128)   (gi_n: agg half only)
//     bn==3 -> k in [128,256) (gh_n: h half only)
#define BM 128
#define BN 128
#define BK 16
#define TM 8
#define TN 8

__global__ __launch_bounds__(256, 2)
void gemm_kernel(const float* __restrict__ A0, const float* __restrict__ A1,
                 int K0, int lda,
                 const float* __restrict__ B, float* __restrict__ D,
                 int M, int N, int K, int gru)
{
    __shared__ float As[2][BK][BM];
    __shared__ float Bs[2][BK][BN];

    const int tid  = threadIdx.x;
    const int bn   = blockIdx.x;
    const int bm   = blockIdx.y;
    const int row0 = bm * BM;
    const int tx   = tid & 15;          // 0..15
    const int ty   = tid >> 4;          // 0..15

    int ks = 0, ke = K;
    if (gru) {
        if (bn == 2) ke = 128;
        else if (bn == 3) ks = 128;
    }

    float4 ra[2], rb[2];

    // --- load one K-tile (kt) from gmem into registers
    auto load_tile = [&](int kt) {
        const float* Aptr; int kloc;
        if (kt < K0) { Aptr = A0; kloc = kt; }
        else         { Aptr = A1; kloc = kt - K0; }
        #pragma unroll
        for (int t = 0; t < 2; t++) {
            int id   = tid + t * 256;           // 0..511
            int arow = id >> 2;                 // 0..127
            int ak   = (id & 3) * 4;            // 0,4,8,12
            int grow = row0 + arow;
            ra[t] = make_float4(0.f, 0.f, 0.f, 0.f);
            if (grow < M)
                ra[t] = *reinterpret_cast<const float4*>(Aptr + (size_t)grow * lda + kloc + ak);
            int brow = id >> 5;                 // 0..15
            int bcol = (id & 31) * 4;           // 0..124
            rb[t] = *reinterpret_cast<const float4*>(B + (size_t)(kt + brow) * N + bn * BN + bcol);
        }
    };
    // --- store staged registers into smem buffer
    auto store_tile = [&](int buf) {
        #pragma unroll
        for (int t = 0; t < 2; t++) {
            int id   = tid + t * 256;
            int arow = id >> 2;
            int ak   = (id & 3) * 4;
            As[buf][ak + 0][arow] = ra[t].x;
            As[buf][ak + 1][arow] = ra[t].y;
            As[buf][ak + 2][arow] = ra[t].z;
            As[buf][ak + 3][arow] = ra[t].w;
            int brow = id >> 5;
            int bcol = (id & 31) * 4;
            *reinterpret_cast<float4*>(&Bs[buf][brow][bcol]) = rb[t];
        }
    };

    float acc[TM][TN];
    #pragma unroll
    for (int i = 0; i < TM; i++)
        #pragma unroll
        for (int j = 0; j < TN; j++) acc[i][j] = 0.0f;

    load_tile(ks);
    store_tile(0);
    __syncthreads();

    int buf = 0;
    for (int kt = ks; kt < ke; kt += BK) {
        const bool nxt = (kt + BK) < ke;
        if (nxt) load_tile(kt + BK);           // LDG overlapped with compute below

        #pragma unroll
        for (int k = 0; k < BK; k++) {
            float4 a0 = *reinterpret_cast<const float4*>(&As[buf][k][ty * TM]);
            float4 a1 = *reinterpret_cast<const float4*>(&As[buf][k][ty * TM + 4]);
            float4 b0 = *reinterpret_cast<const float4*>(&Bs[buf][k][tx * TN]);
            float4 b1 = *reinterpret_cast<const float4*>(&Bs[buf][k][tx * TN + 4]);
            float af[TM] = {a0.x, a0.y, a0.z, a0.w, a1.x, a1.y, a1.z, a1.w};
            float bf[TN] = {b0.x, b0.y, b0.z, b0.w, b1.x, b1.y, b1.z, b1.w};
            #pragma unroll
            for (int i = 0; i < TM; i++)
                #pragma unroll
                for (int j = 0; j < TN; j++)
                    acc[i][j] += af[i] * bf[j];
        }

        if (nxt) {
            __syncthreads();                   // everyone done reading smem[buf^1] (1 iter ago)
            store_tile(buf ^ 1);
            __syncthreads();
            buf ^= 1;
        }
    }

    #pragma unroll
    for (int i = 0; i < TM; i++) {
        int grow = row0 + ty * TM + i;
        if (grow < M) {
            float* dp = D + (size_t)grow * N + bn * BN + tx * TN;
            *reinterpret_cast<float4*>(dp)     = make_float4(acc[i][0], acc[i][1], acc[i][2], acc[i][3]);
            *reinterpret_cast<float4*>(dp + 4) = make_float4(acc[i][4], acc[i][5], acc[i][6], acc[i][7]);
        }
    }
}

// ---------------- scatter-add: one warp per edge --------------------------
__global__ __launch_bounds__(256)
void scatter_kernel(const int* __restrict__ sd,
                    const float* __restrict__ m,
                    float* __restrict__ agg, int nE)
{
    int warp = (blockIdx.x * blockDim.x + threadIdx.x) >> 5;
    int lane = threadIdx.x & 31;
    if (warp >= nE) return;
    int s = sd[warp];           // src
    int d = sd[nE + warp];      // dst
    float4 v = *reinterpret_cast<const float4*>(m + (size_t)s * CH + lane * 4);
    float* dp = agg + (size_t)d * CH + lane * 4;
    asm volatile("red.global.add.v4.f32 [%0], {%1, %2, %3, %4};"
                 :: "l"(dp), "f"(v.x), "f"(v.y), "f"(v.z), "f"(v.w)
                 : "memory");
}

// ---------------- GRU gate epilogue ---------------------------------------
__global__ void gates_kernel(const float* __restrict__ G,
                             const float* __restrict__ b_ih,
                             const float* __restrict__ b_hh,
                             float* __restrict__ h, int nN)
{
    int idx = blockIdx.x * blockDim.x + threadIdx.x;
    if (idx >= nN * CH) return;
    int n = idx >> 7;
    int c = idx & 127;
    const float* g = G + (size_t)n * GW;
    float r   = 1.0f / (1.0f + expf(-(g[c]       + b_ih[c]       + b_hh[c])));
    float z   = 1.0f / (1.0f + expf(-(g[128 + c] + b_ih[128 + c] + b_hh[128 + c])));
    float gin = g[256 + c] + b_ih[256 + c];
    float ghn = g[384 + c] + b_hh[256 + c];
    float nn  = tanhf(gin + r * ghn);
    float ho  = h[idx];
    h[idx] = (1.0f - z) * nn + z * ho;
}

// ---------------- readout --------------------------------------------------
__global__ void reduce_kernel(const float* __restrict__ h, float* __restrict__ gsum, int nN)
{
    int c = threadIdx.x;    // 128 threads/block, one channel each
    float acc = 0.0f;
    for (int n = blockIdx.x; n < nN; n += gridDim.x) {
        float v = h[(size_t)n * CH + c];
        v = (v >= 0.0f) ? v : 0.01f * v;      // LeakyReLU
        acc += v;
    }
    atomicAdd(&gsum[c], acc);
}

__global__ void final_kernel(const float* __restrict__ gsum,
                             const float* __restrict__ W_pred,
                             const float* __restrict__ b_pred,
                             float* __restrict__ out, float invN)
{
    __shared__ float s[CH];
    int t = threadIdx.x;
    s[t] = gsum[t] * invN * W_pred[t];
    __syncthreads();
    #pragma unroll
    for (int o = 64; o > 0; o >>= 1) {
        if (t < o) s[t] += s[t + o];
        __syncthreads();
    }
    if (t == 0) out[0] = s[0] + b_pred[0];
}

// ---------------- launch ----------------------------------------------------
extern "C" void kernel_launch(void* const* d_in, const int* in_sizes, int n_in,
                              void* d_out, int out_size)
{
    const float*  x      = (const float*)d_in[0];
    const void*   ei     = d_in[1];                  // int32 or int64 node ids
    const float*  W_in   = (const float*)d_in[2];
    const float*  W_mpnn = (const float*)d_in[3];
    const float*  W_ih   = (const float*)d_in[4];
    const float*  W_hh   = (const float*)d_in[5];
    const float*  b_ih   = (const float*)d_in[6];
    const float*  b_hh   = (const float*)d_in[7];
    const float*  W_pred = (const float*)d_in[8];
    const float*  b_pred = (const float*)d_in[9];
    float*        out    = (float*)d_out;
    (void)n_in; (void)out_size;

    const int nN = in_sizes[0] / FIN;      // 100000
    const int nE = in_sizes[1] / 2;        // 1600000

    float *p_h, *p_m, *p_agg, *p_G, *p_Wall, *p_WinT, *p_gsum;
    int *p_sd, *p_flag;
    cudaGetSymbolAddress((void**)&p_h,    g_h);
    cudaGetSymbolAddress((void**)&p_m,    g_m);
    cudaGetSymbolAddress((void**)&p_agg,  g_agg);
    cudaGetSymbolAddress((void**)&p_G,    g_G);
    cudaGetSymbolAddress((void**)&p_Wall, g_Wall);
    cudaGetSymbolAddress((void**)&p_WinT, g_WinT);
    cudaGetSymbolAddress((void**)&p_gsum, g_gsum);
    cudaGetSymbolAddress((void**)&p_sd,   g_sd);
    cudaGetSymbolAddress((void**)&p_flag, g_idx64);

    const int mtiles = (nN + BM - 1) / BM;

    // prep: edge-index normalization + weight repacking
    detect_idx_kernel<<<1, 512>>>((const int*)ei, p_flag);
    convert_idx_kernel<<<(2 * nE + 255) / 256, 256>>>(ei, p_sd, p_flag, 2 * nE);
    prep_wint_kernel<<<(FIN * CH + 255) / 256, 256>>>(W_in, p_WinT);
    prep_wall_kernel<<<(256 * GW + 255) / 256, 256>>>(W_ih, W_hh, p_Wall);

    // h = x @ W_in^T     [nN,64] @ [64,128]
    {
        dim3 grid(CH / BN, mtiles);
        gemm_kernel<<<grid, 256>>>(x, x, FIN, FIN, p_WinT, p_h, nN, CH, FIN, 0);
    }

    for (int i = 0; i < STEPS; i++) {
        // m = h @ W_mpnn[i]       [nN,128] @ [128,128]
        {
            dim3 grid(CH / BN, mtiles);
            gemm_kernel<<<grid, 256>>>(p_h, p_h, CH, CH,
                                       W_mpnn + (size_t)i * CH * CH, p_m, nN, CH, CH, 0);
        }
        // agg = scatter_add(m[src] -> dst)
        cudaMemsetAsync(p_agg, 0, (size_t)nN * CH * sizeof(float));
        {
            int warps_per_block = 256 / 32;
            int blocks = (nE + warps_per_block - 1) / warps_per_block;
            scatter_kernel<<<blocks, 256>>>(p_sd, p_m, p_agg, nE);
        }
        // G = [agg|h] @ Wall      [nN,256] @ [256,512]  (zero-blocks skipped)
        {
            dim3 grid(GW / BN, mtiles);
            gemm_kernel<<<grid, 256>>>(p_agg, p_h, CH, CH, p_Wall, p_G, nN, GW, 2 * CH, 1);
        }
        // GRU gate update (in-place on h)
        gates_kernel<<<(nN * CH + 255) / 256, 256>>>(p_G, b_ih, b_hh, p_h, nN);
    }

    // readout: LeakyReLU -> mean -> linear
    cudaMemsetAsync(p_gsum, 0, CH * sizeof(float));
    reduce_kernel<<<2048, CH>>>(p_h, p_gsum, nN);
    final_kernel<<<1, CH>>>(p_gsum, W_pred, b_pred, out, 1.0f / (float)nN);
}

// round 7
// speedup vs baseline: 2.3440x; 1.8073x over previous
#include <cuda_runtime.h>
#include <cuda_bf16.h>
#include <math.h>
#include <stdint.h>

// Problem constants
#define FIN    64
#define CH     128
#define STEPS  4
#define NMAX   100096       // 100000 padded to multiple of 128
#define NEMAX  1600000
#define GW     512          // GRU GEMM output width (4*C)

// ---------------- scratch (static device allocations) ----------------------
__device__ float g_h   [(size_t)NMAX * CH];
__device__ float g_m   [(size_t)NMAX * CH];
__device__ float g_agg [(size_t)NMAX * CH];
__device__ float g_G   [(size_t)NMAX * GW];
__device__ float g_gsum[CH];
__device__ int   g_sd  [2 * NEMAX];
__device__ int   g_idx64;
__device__ int   g_deg [NMAX];
__device__ int   g_pref[NMAX];
__device__ int   g_cur [NMAX];
__device__ int   g_col [NEMAX];
__device__ int   g_bsum[128];
// pre-packed bf16 hi/lo weights, all [N, K] K-major (row-major, K contiguous)
__device__ __nv_bfloat16 g_Bemb_hi[CH * FIN],        g_Bemb_lo[CH * FIN];
__device__ __nv_bfloat16 g_Bmp_hi [STEPS * CH * CH], g_Bmp_lo [STEPS * CH * CH];
__device__ __nv_bfloat16 g_Bgru_hi[GW * 256],        g_Bgru_lo[GW * 256];

// ---------------- helpers ---------------------------------------------------
__device__ __forceinline__ uint32_t smem_u32(const void* p) {
    uint32_t a;
    asm("{ .reg .u64 t; cvta.to.shared.u64 t, %1; cvt.u32.u64 %0, t; }" : "=r"(a) : "l"(p));
    return a;
}
__device__ __forceinline__ unsigned short bfhi(float a) {
    return __bfloat16_as_ushort(__float2bfloat16_rn(a));
}
__device__ __forceinline__ unsigned short bflo(float a) {
    __nv_bfloat16 h = __float2bfloat16_rn(a);
    return __bfloat16_as_ushort(__float2bfloat16_rn(a - __bfloat162float(h)));
}
__device__ __forceinline__ void ldm4(uint32_t& r0, uint32_t& r1, uint32_t& r2, uint32_t& r3, uint32_t a) {
    asm volatile("ldmatrix.sync.aligned.m8n8.x4.shared.b16 {%0,%1,%2,%3}, [%4];"
        : "=r"(r0), "=r"(r1), "=r"(r2), "=r"(r3) : "r"(a));
}
__device__ __forceinline__ void mma_bf16(float* d, const uint32_t* a, const uint32_t* b) {
    asm volatile("mma.sync.aligned.m16n8k16.row.col.f32.bf16.bf16.f32 "
        "{%0,%1,%2,%3}, {%4,%5,%6,%7}, {%8,%9}, {%0,%1,%2,%3};"
        : "+f"(d[0]), "+f"(d[1]), "+f"(d[2]), "+f"(d[3])
        : "r"(a[0]), "r"(a[1]), "r"(a[2]), "r"(a[3]), "r"(b[0]), "r"(b[1]));
}

// ---------------- edge-index dtype detection / normalization ---------------
__global__ void detect_idx_kernel(const int* __restrict__ w, int* __restrict__ flag)
{
    __shared__ int s_any;
    if (threadIdx.x == 0) s_any = 0;
    __syncthreads();
    int v = w[2 * threadIdx.x + 1];
    if (v != 0) atomicOr(&s_any, 1);
    __syncthreads();
    if (threadIdx.x == 0) *flag = (s_any == 0) ? 1 : 0;   // all odd words zero -> int64
}

__global__ void convert_idx_kernel(const void* __restrict__ ei,
                                   int* __restrict__ sd,
                                   const int* __restrict__ flag, int total)
{
    int i = blockIdx.x * blockDim.x + threadIdx.x;
    if (i >= total) return;
    if (*flag) sd[i] = (int)((const long long*)ei)[i];
    else       sd[i] = ((const int*)ei)[i];
}

// ---------------- CSR build -------------------------------------------------
__global__ void hist_kernel(const int* __restrict__ sd, int* __restrict__ deg, int nE)
{
    int i = blockIdx.x * blockDim.x + threadIdx.x;
    if (i < nE) atomicAdd(&deg[sd[nE + i]], 1);
}

// 1024 items per block, 256 threads x 4
__global__ void scan1_kernel(const int* __restrict__ deg, int* __restrict__ pref,
                             int* __restrict__ bsum, int nN)
{
    __shared__ int sh[256];
    int base = blockIdx.x * 1024;
    int t = threadIdx.x;
    int v[4]; int s = 0;
    #pragma unroll
    for (int q = 0; q < 4; q++) {
        int idx = base + t * 4 + q;
        v[q] = (idx < nN) ? deg[idx] : 0;
        s += v[q];
    }
    sh[t] = s; __syncthreads();
    for (int o = 1; o < 256; o <<= 1) {
        int x = (t >= o) ? sh[t - o] : 0;
        __syncthreads();
        sh[t] += x;
        __syncthreads();
    }
    int run = sh[t] - s;          // exclusive prefix of this thread's group
    #pragma unroll
    for (int q = 0; q < 4; q++) {
        int idx = base + t * 4 + q;
        if (idx < nN) pref[idx] = run;
        run += v[q];
    }
    if (t == 255) bsum[blockIdx.x] = sh[255];
}

__global__ void scan2_kernel(int* __restrict__ bsum, int nb)
{
    if (threadIdx.x == 0) {
        int acc = 0;
        for (int i = 0; i < nb; i++) { int v = bsum[i]; bsum[i] = acc; acc += v; }
    }
}

__global__ void scan3_kernel(int* __restrict__ pref, const int* __restrict__ bsum,
                             int* __restrict__ cur, int nN)
{
    int i = blockIdx.x * blockDim.x + threadIdx.x;
    if (i < nN) {
        int v = pref[i] + bsum[i >> 10];
        pref[i] = v;
        cur[i] = v;
    }
}

__global__ void fill_kernel(const int* __restrict__ sd, int* __restrict__ cur,
                            int* __restrict__ col, int nE)
{
    int i = blockIdx.x * blockDim.x + threadIdx.x;
    if (i < nE) {
        int d = sd[nE + i];
        int pos = atomicAdd(&cur[d], 1);
        col[pos] = sd[i];
    }
}

// ---------------- CSR aggregation: one warp per dst node -------------------
__global__ __launch_bounds__(256)
void aggregate_kernel(const int* __restrict__ pref, const int* __restrict__ deg,
                      const int* __restrict__ col, const float* __restrict__ m,
                      float* __restrict__ agg, int nN)
{
    int w = (blockIdx.x * blockDim.x + threadIdx.x) >> 5;
    int lane = threadIdx.x & 31;
    if (w >= nN) return;
    int st = pref[w], dg = deg[w];
    float4 a = make_float4(0.f, 0.f, 0.f, 0.f);
    for (int j = 0; j < dg; j++) {
        int s = col[st + j];
        float4 v = *reinterpret_cast<const float4*>(m + (size_t)s * CH + lane * 4);
        a.x += v.x; a.y += v.y; a.z += v.z; a.w += v.w;
    }
    *reinterpret_cast<float4*>(agg + (size_t)w * CH + lane * 4) = a;
}

// ---------------- weight packing (fp32 -> bf16 hi/lo, [N,K]) ---------------
__global__ void prep_bemb(const float* __restrict__ W_in,
                          __nv_bfloat16* __restrict__ hi, __nv_bfloat16* __restrict__ lo) {
    int i = blockIdx.x * blockDim.x + threadIdx.x;
    if (i >= CH * FIN) return;          // W_in already [n=C][k=F_IN]
    float v = W_in[i];
    hi[i] = __float2bfloat16_rn(v);
    lo[i] = __float2bfloat16_rn(v - __bfloat162float(__float2bfloat16_rn(v)));
}

__global__ void prep_bmp(const float* __restrict__ W,
                         __nv_bfloat16* __restrict__ hi, __nv_bfloat16* __restrict__ lo) {
    int i = blockIdx.x * blockDim.x + threadIdx.x;
    if (i >= STEPS * CH * CH) return;   // out[s][n][k] = W[s][k][n]
    int s = i / (CH * CH), r = i % (CH * CH), n = r / CH, k = r % CH;
    float v = W[s * CH * CH + k * CH + n];
    hi[i] = __float2bfloat16_rn(v);
    lo[i] = __float2bfloat16_rn(v - __bfloat162float(__float2bfloat16_rn(v)));
}

__global__ void prep_bgru(const float* __restrict__ W_ih, const float* __restrict__ W_hh,
                          __nv_bfloat16* __restrict__ hi, __nv_bfloat16* __restrict__ lo) {
    int i = blockIdx.x * blockDim.x + threadIdx.x;
    if (i >= GW * 256) return;          // [n=512][k=256]
    int n = i >> 8, k = i & 255;
    float v = 0.0f;
    if (n < 256)      v = (k < 128) ? W_ih[n * CH + k] : W_hh[n * CH + (k - 128)];
    else if (n < 384) v = (k < 128) ? W_ih[n * CH + k] : 0.0f;                    // gi_n
    else              v = (k >= 128) ? W_hh[(n - 128) * CH + (k - 128)] : 0.0f;   // gh_n
    hi[i] = __float2bfloat16_rn(v);
    lo[i] = __float2bfloat16_rn(v - __bfloat162float(__float2bfloat16_rn(v)));
}

// ---------------- bf16-split mma.sync GEMM ---------------------------------
//  D[M,Ntot](fp32) = A[M,K](fp32) @ B[K,N] via Ahi*Bhi + Ahi*Blo + Alo*Bhi
//  A split across A0 (k<K0) / A1 (k>=K0), row-major, leading dim lda.
//  B pre-packed bf16 hi/lo as [Ntot, K] row-major (K contiguous), lead ldb.
//  CTA tile 128x128, BK=32, 8 warps (4m x 2n), warp tile 32x64.
#define PITCH 80
#define SA_HI(b) ((b) * 40960 + 0)
#define SA_LO(b) ((b) * 40960 + 10240)
#define SB_HI(b) ((b) * 40960 + 20480)
#define SB_LO(b) ((b) * 40960 + 30720)
#define GEMM_SMEM 81920

__global__ __launch_bounds__(256)
void gemm_mma(const float* __restrict__ A0, const float* __restrict__ A1, int K0, int lda,
              const __nv_bfloat16* __restrict__ Bhi, const __nv_bfloat16* __restrict__ Blo, int ldb,
              float* __restrict__ D, int M, int Ntot, int K, int gru)
{
    extern __shared__ char smem[];
    const uint32_t sb = smem_u32(smem);
    const int tid  = threadIdx.x;
    const int lane = tid & 31;
    const int wid  = tid >> 5;
    const int wm   = wid & 3;           // 4 m-warps: rows wm*32
    const int wn   = wid >> 2;          // 2 n-warps: cols wn*64
    const int bn   = blockIdx.x, bm = blockIdx.y;
    const int row0 = bm * 128, ncol0 = bn * 128;

    int ks = 0, ke = K;
    if (gru) { if (bn == 2) ke = 128; else if (bn == 3) ks = 128; }
    const int nkc = (ke - ks) >> 5;     // BK=32 chunks

    // fill indexing: 2 threads per row, 16 k each
    const int frow  = tid >> 1;
    const int fhalf = tid & 1;

    float4 sa[4];                       // 16 fp32 of A
    uint4  sbh[2], sbl[2];              // 16 bf16 hi + 16 bf16 lo of B

    auto load_stage = [&](int kt) {
        const float* Ap; int kb;
        if (kt < K0) { Ap = A0; kb = kt; } else { Ap = A1; kb = kt - K0; }
        const float* asrc = Ap + (size_t)(row0 + frow) * lda + kb + fhalf * 16;
        if (row0 + frow < M) {
            sa[0] = *(const float4*)(asrc + 0);
            sa[1] = *(const float4*)(asrc + 4);
            sa[2] = *(const float4*)(asrc + 8);
            sa[3] = *(const float4*)(asrc + 12);
        } else {
            sa[0] = sa[1] = sa[2] = sa[3] = make_float4(0.f, 0.f, 0.f, 0.f);
        }
        const __nv_bfloat16* bh = Bhi + (size_t)(ncol0 + frow) * ldb + kt + fhalf * 16;
        const __nv_bfloat16* bl = Blo + (size_t)(ncol0 + frow) * ldb + kt + fhalf * 16;
        sbh[0] = *(const uint4*)(bh);     sbh[1] = *(const uint4*)(bh + 8);
        sbl[0] = *(const uint4*)(bl);     sbl[1] = *(const uint4*)(bl + 8);
    };

    auto store_stage = [&](int b) {
        char* ah = smem + SA_HI(b) + frow * PITCH + fhalf * 32;
        char* al = smem + SA_LO(b) + frow * PITCH + fhalf * 32;
        #pragma unroll
        for (int q = 0; q < 4; q++) {
            ushort4 oh, ol;
            oh.x = bfhi(sa[q].x); oh.y = bfhi(sa[q].y); oh.z = bfhi(sa[q].z); oh.w = bfhi(sa[q].w);
            ol.x = bflo(sa[q].x); ol.y = bflo(sa[q].y); ol.z = bflo(sa[q].z); ol.w = bflo(sa[q].w);
            *(ushort4*)(ah + q * 8) = oh;
            *(ushort4*)(al + q * 8) = ol;
        }
        char* bh = smem + SB_HI(b) + frow * PITCH + fhalf * 32;
        char* bl = smem + SB_LO(b) + frow * PITCH + fhalf * 32;
        *(uint4*)(bh)      = sbh[0];  *(uint4*)(bh + 16) = sbh[1];
        *(uint4*)(bl)      = sbl[0];  *(uint4*)(bl + 16) = sbl[1];
    };

    float acc[2][8][4];
    #pragma unroll
    for (int i = 0; i < 2; i++)
        #pragma unroll
        for (int j = 0; j < 8; j++)
            #pragma unroll
            for (int q = 0; q < 4; q++) acc[i][j][q] = 0.0f;

    const int lt = lane >> 3;           // ldmatrix tile id 0..3
    const int lr = lane & 7;            // row within tile

    load_stage(ks);
    store_stage(0);
    __syncthreads();

    for (int c = 0; c < nkc; c++) {
        const int b = c & 1;
        const bool nxt = (c + 1) < nkc;
        if (nxt) load_stage(ks + (c + 1) * 32);

        #pragma unroll
        for (int c16 = 0; c16 < 2; c16++) {
            uint32_t ah[2][4], al[2][4], bhf[8][2], blf[8][2];
            #pragma unroll
            for (int mt = 0; mt < 2; mt++) {
                int mrow = wm * 32 + mt * 16 + ((lt & 1) << 3) + lr;
                uint32_t off = (uint32_t)(mrow * PITCH + c16 * 32 + ((lt >> 1) << 4));
                ldm4(ah[mt][0], ah[mt][1], ah[mt][2], ah[mt][3], sb + SA_HI(b) + off);
                ldm4(al[mt][0], al[mt][1], al[mt][2], al[mt][3], sb + SA_LO(b) + off);
            }
            #pragma unroll
            for (int np = 0; np < 4; np++) {
                int nrow = wn * 64 + np * 16 + ((lt >> 1) << 3) + lr;
                uint32_t off = (uint32_t)(nrow * PITCH + c16 * 32 + ((lt & 1) << 4));
                uint32_t r0, r1, r2, r3;
                ldm4(r0, r1, r2, r3, sb + SB_HI(b) + off);
                bhf[2 * np][0] = r0; bhf[2 * np][1] = r1;
                bhf[2 * np + 1][0] = r2; bhf[2 * np + 1][1] = r3;
                ldm4(r0, r1, r2, r3, sb + SB_LO(b) + off);
                blf[2 * np][0] = r0; blf[2 * np][1] = r1;
                blf[2 * np + 1][0] = r2; blf[2 * np + 1][1] = r3;
            }
            #pragma unroll
            for (int mt = 0; mt < 2; mt++)
                #pragma unroll
                for (int nt = 0; nt < 8; nt++) {
                    mma_bf16(acc[mt][nt], ah[mt], bhf[nt]);   // Ahi*Bhi
                    mma_bf16(acc[mt][nt], ah[mt], blf[nt]);   // Ahi*Blo
                    mma_bf16(acc[mt][nt], al[mt], bhf[nt]);   // Alo*Bhi
                }
        }
        __syncthreads();
        if (nxt) { store_stage(b ^ 1); __syncthreads(); }
    }

    // epilogue: direct STG from fragments
    #pragma unroll
    for (int mt = 0; mt < 2; mt++)
        #pragma unroll
        for (int nt = 0; nt < 8; nt++) {
            int r_ = row0 + wm * 32 + mt * 16 + (lane >> 2);
            int cc = ncol0 + wn * 64 + nt * 8 + ((lane & 3) << 1);
            if (r_ < M)
                *(float2*)(D + (size_t)r_ * Ntot + cc) = make_float2(acc[mt][nt][0], acc[mt][nt][1]);
            if (r_ + 8 < M)
                *(float2*)(D + (size_t)(r_ + 8) * Ntot + cc) = make_float2(acc[mt][nt][2], acc[mt][nt][3]);
        }
}

// ---------------- GRU gate epilogue ----------------------------------------
__global__ void gates_kernel(const float* __restrict__ G,
                             const float* __restrict__ b_ih,
                             const float* __restrict__ b_hh,
                             float* __restrict__ h, int nN)
{
    int idx = blockIdx.x * blockDim.x + threadIdx.x;
    if (idx >= nN * CH) return;
    int n = idx >> 7;
    int c = idx & 127;
    const float* g = G + (size_t)n * GW;
    float r   = 1.0f / (1.0f + expf(-(g[c]       + b_ih[c]       + b_hh[c])));
    float z   = 1.0f / (1.0f + expf(-(g[128 + c] + b_ih[128 + c] + b_hh[128 + c])));
    float gin = g[256 + c] + b_ih[256 + c];
    float ghn = g[384 + c] + b_hh[256 + c];
    float nn  = tanhf(gin + r * ghn);
    float ho  = h[idx];
    h[idx] = (1.0f - z) * nn + z * ho;
}

// ---------------- readout --------------------------------------------------
__global__ void reduce_kernel(const float* __restrict__ h, float* __restrict__ gsum, int nN)
{
    int c = threadIdx.x;
    float acc = 0.0f;
    for (int n = blockIdx.x; n < nN; n += gridDim.x) {
        float v = h[(size_t)n * CH + c];
        v = (v >= 0.0f) ? v : 0.01f * v;
        acc += v;
    }
    atomicAdd(&gsum[c], acc);
}

__global__ void final_kernel(const float* __restrict__ gsum,
                             const float* __restrict__ W_pred,
                             const float* __restrict__ b_pred,
                             float* __restrict__ out, float invN)
{
    __shared__ float s[CH];
    int t = threadIdx.x;
    s[t] = gsum[t] * invN * W_pred[t];
    __syncthreads();
    #pragma unroll
    for (int o = 64; o > 0; o >>= 1) {
        if (t < o) s[t] += s[t + o];
        __syncthreads();
    }
    if (t == 0) out[0] = s[0] + b_pred[0];
}

// ---------------- launch ----------------------------------------------------
extern "C" void kernel_launch(void* const* d_in, const int* in_sizes, int n_in,
                              void* d_out, int out_size)
{
    const float*  x      = (const float*)d_in[0];
    const void*   ei     = d_in[1];
    const float*  W_in   = (const float*)d_in[2];
    const float*  W_mpnn = (const float*)d_in[3];
    const float*  W_ih   = (const float*)d_in[4];
    const float*  W_hh   = (const float*)d_in[5];
    const float*  b_ih   = (const float*)d_in[6];
    const float*  b_hh   = (const float*)d_in[7];
    const float*  W_pred = (const float*)d_in[8];
    const float*  b_pred = (const float*)d_in[9];
    float*        out    = (float*)d_out;
    (void)n_in; (void)out_size;

    const int nN = in_sizes[0] / FIN;      // 100000
    const int nE = in_sizes[1] / 2;        // 1600000

    float *p_h, *p_m, *p_agg, *p_G, *p_gsum;
    int *p_sd, *p_flag, *p_deg, *p_pref, *p_cur, *p_col, *p_bsum;
    __nv_bfloat16 *p_beh, *p_bel, *p_bmh, *p_bml, *p_bgh, *p_bgl;
    cudaGetSymbolAddress((void**)&p_h,    g_h);
    cudaGetSymbolAddress((void**)&p_m,    g_m);
    cudaGetSymbolAddress((void**)&p_agg,  g_agg);
    cudaGetSymbolAddress((void**)&p_G,    g_G);
    cudaGetSymbolAddress((void**)&p_gsum, g_gsum);
    cudaGetSymbolAddress((void**)&p_sd,   g_sd);
    cudaGetSymbolAddress((void**)&p_flag, g_idx64);
    cudaGetSymbolAddress((void**)&p_deg,  g_deg);
    cudaGetSymbolAddress((void**)&p_pref, g_pref);
    cudaGetSymbolAddress((void**)&p_cur,  g_cur);
    cudaGetSymbolAddress((void**)&p_col,  g_col);
    cudaGetSymbolAddress((void**)&p_bsum, g_bsum);
    cudaGetSymbolAddress((void**)&p_beh,  g_Bemb_hi);
    cudaGetSymbolAddress((void**)&p_bel,  g_Bemb_lo);
    cudaGetSymbolAddress((void**)&p_bmh,  g_Bmp_hi);
    cudaGetSymbolAddress((void**)&p_bml,  g_Bmp_lo);
    cudaGetSymbolAddress((void**)&p_bgh,  g_Bgru_hi);
    cudaGetSymbolAddress((void**)&p_bgl,  g_Bgru_lo);

    cudaFuncSetAttribute(gemm_mma, cudaFuncAttributeMaxDynamicSharedMemorySize, GEMM_SMEM);

    const int mtiles = (nN + 127) / 128;
    const int nb = (nN + 1023) / 1024;

    // --- prep: edge normalization + CSR build + weight packing
    detect_idx_kernel<<<1, 512>>>((const int*)ei, p_flag);
    convert_idx_kernel<<<(2 * nE + 255) / 256, 256>>>(ei, p_sd, p_flag, 2 * nE);
    cudaMemsetAsync(p_deg, 0, (size_t)nN * sizeof(int));
    hist_kernel<<<(nE + 255) / 256, 256>>>(p_sd, p_deg, nE);
    scan1_kernel<<<nb, 256>>>(p_deg, p_pref, p_bsum, nN);
    scan2_kernel<<<1, 32>>>(p_bsum, nb);
    scan3_kernel<<<(nN + 255) / 256, 256>>>(p_pref, p_bsum, p_cur, nN);
    fill_kernel<<<(nE + 255) / 256, 256>>>(p_sd, p_cur, p_col, nE);
    prep_bemb<<<(CH * FIN + 255) / 256, 256>>>(W_in, p_beh, p_bel);
    prep_bmp <<<(STEPS * CH * CH + 255) / 256, 256>>>(W_mpnn, p_bmh, p_bml);
    prep_bgru<<<(GW * 256 + 255) / 256, 256>>>(W_ih, W_hh, p_bgh, p_bgl);

    // h = x @ W_in^T     [nN,64] x [64,128]
    gemm_mma<<<dim3(1, mtiles), 256, GEMM_SMEM>>>(
        x, x, FIN, FIN, p_beh, p_bel, FIN, p_h, nN, CH, FIN, 0);

    for (int i = 0; i < STEPS; i++) {
        // m = h @ W_mpnn[i]   [nN,128] x [128,128]
        gemm_mma<<<dim3(1, mtiles), 256, GEMM_SMEM>>>(
            p_h, p_h, CH, CH,
            p_bmh + (size_t)i * CH * CH, p_bml + (size_t)i * CH * CH, CH,
            p_m, nN, CH, CH, 0);

        // agg = CSR-aggregate(m[src] -> dst)
        aggregate_kernel<<<(nN * 32 + 255) / 256, 256>>>(p_pref, p_deg, p_col, p_m, p_agg, nN);

        // G = [agg|h] @ Wgru  [nN,256] x [256,512] with zero-blocks skipped
        gemm_mma<<<dim3(4, mtiles), 256, GEMM_SMEM>>>(
            p_agg, p_h, CH, CH, p_bgh, p_bgl, 256, p_G, nN, GW, 2 * CH, 1);

        // GRU gate update (in-place on h)
        gates_kernel<<<(nN * CH + 255) / 256, 256>>>(p_G, b_ih, b_hh, p_h, nN);
    }

    // readout
    cudaMemsetAsync(p_gsum, 0, CH * sizeof(float));
    reduce_kernel<<<2048, CH>>>(p_h, p_gsum, nN);
    final_kernel<<<1, CH>>>(p_gsum, W_pred, b_pred, out, 1.0f / (float)nN);
}

// round 8
// speedup vs baseline: 2.6561x; 1.1331x over previous
#include <cuda_runtime.h>
#include <cuda_bf16.h>
#include <math.h>
#include <stdint.h>

// Problem constants
#define FIN    64
#define CH     128
#define STEPS  4
#define NMAX   100096       // 100000 padded to multiple of 128
#define NEMAX  1600000
#define GW     512          // GRU GEMM output width

// ---------------- scratch (static device allocations) ----------------------
__device__ float g_h   [(size_t)NMAX * CH];
__device__ float g_agg [(size_t)NMAX * CH];
__device__ float g_G   [(size_t)NMAX * GW];
__device__ float g_gsum[CH];
__device__ float g_W2  [STEPS * CH * 384];       // W_mpnn[i] @ W_ih^T
__device__ int   g_sd  [2 * NEMAX];
__device__ int   g_idx64;
__device__ int   g_deg [NMAX];
__device__ int   g_pref[NMAX];
__device__ int   g_cur [NMAX];
__device__ int   g_col [NEMAX];
__device__ int   g_bsum[128];
// pre-packed bf16 hi/lo weights, [N, K] K-major
__device__ __nv_bfloat16 g_Bemb_hi[CH * FIN],  g_Bemb_lo[CH * FIN];
__device__ __nv_bfloat16 g_Bgru_hi[STEPS * GW * 256], g_Bgru_lo[STEPS * GW * 256];

// ---------------- helpers ---------------------------------------------------
__device__ __forceinline__ uint32_t smem_u32(const void* p) {
    uint32_t a;
    asm("{ .reg .u64 t; cvta.to.shared.u64 t, %1; cvt.u32.u64 %0, t; }" : "=r"(a) : "l"(p));
    return a;
}
__device__ __forceinline__ unsigned short bfhi(float a) {
    return __bfloat16_as_ushort(__float2bfloat16_rn(a));
}
__device__ __forceinline__ unsigned short bflo(float a) {
    __nv_bfloat16 h = __float2bfloat16_rn(a);
    return __bfloat16_as_ushort(__float2bfloat16_rn(a - __bfloat162float(h)));
}
__device__ __forceinline__ void ldm4(uint32_t& r0, uint32_t& r1, uint32_t& r2, uint32_t& r3, uint32_t a) {
    asm volatile("ldmatrix.sync.aligned.m8n8.x4.shared.b16 {%0,%1,%2,%3}, [%4];"
        : "=r"(r0), "=r"(r1), "=r"(r2), "=r"(r3) : "r"(a));
}
__device__ __forceinline__ void mma_bf16(float* d, const uint32_t* a, const uint32_t* b) {
    asm volatile("mma.sync.aligned.m16n8k16.row.col.f32.bf16.bf16.f32 "
        "{%0,%1,%2,%3}, {%4,%5,%6,%7}, {%8,%9}, {%0,%1,%2,%3};"
        : "+f"(d[0]), "+f"(d[1]), "+f"(d[2]), "+f"(d[3])
        : "r"(a[0]), "r"(a[1]), "r"(a[2]), "r"(a[3]), "r"(b[0]), "r"(b[1]));
}

// ---------------- edge-index dtype detection / normalization ---------------
__global__ void detect_idx_kernel(const int* __restrict__ w, int* __restrict__ flag)
{
    __shared__ int s_any;
    if (threadIdx.x == 0) s_any = 0;
    __syncthreads();
    int v = w[2 * threadIdx.x + 1];
    if (v != 0) atomicOr(&s_any, 1);
    __syncthreads();
    if (threadIdx.x == 0) *flag = (s_any == 0) ? 1 : 0;   // all odd words zero -> int64
}

__global__ void convert_idx_kernel(const void* __restrict__ ei,
                                   int* __restrict__ sd,
                                   const int* __restrict__ flag, int total)
{
    int i = blockIdx.x * blockDim.x + threadIdx.x;
    if (i >= total) return;
    if (*flag) sd[i] = (int)((const long long*)ei)[i];
    else       sd[i] = ((const int*)ei)[i];
}

// ---------------- weight prep ----------------------------------------------
__global__ void prep_bemb(const float* __restrict__ W_in,
                          __nv_bfloat16* __restrict__ hi, __nv_bfloat16* __restrict__ lo) {
    int i = blockIdx.x * blockDim.x + threadIdx.x;
    if (i >= CH * FIN) return;          // W_in already [n=C][k=F_IN]
    float v = W_in[i];
    hi[i] = __float2bfloat16_rn(v);
    lo[i] = __float2bfloat16_rn(v - __bfloat162float(__float2bfloat16_rn(v)));
}

// W2[s][ci][o] = sum_co W_mpnn[s][ci][co] * W_ih[o][co]    (o < 384)
__global__ void prep_w2(const float* __restrict__ W_mpnn, const float* __restrict__ W_ih,
                        float* __restrict__ W2) {
    int i = blockIdx.x * blockDim.x + threadIdx.x;
    if (i >= STEPS * CH * 384) return;
    int s = i / (CH * 384), r = i % (CH * 384), ci = r / 384, o = r % 384;
    const float* wm = W_mpnn + (size_t)s * CH * CH + (size_t)ci * CH;
    const float* wi = W_ih + (size_t)o * CH;
    float acc = 0.0f;
    #pragma unroll 8
    for (int co = 0; co < CH; co++) acc += wm[co] * wi[co];
    W2[i] = acc;
}

// per-step combined GRU weights [s][n=512][k=256] from W2[s] and W_hh
__global__ void prep_bgru(const float* __restrict__ W2, const float* __restrict__ W_hh,
                          __nv_bfloat16* __restrict__ hi, __nv_bfloat16* __restrict__ lo) {
    int i = blockIdx.x * blockDim.x + threadIdx.x;
    if (i >= STEPS * GW * 256) return;
    int s = i / (GW * 256), r = i % (GW * 256), n = r >> 8, k = r & 255;
    float v = 0.0f;
    if (n < 384) {
        if (k < 128) v = W2[(size_t)s * CH * 384 + (size_t)k * 384 + n];
        else if (n < 256) v = W_hh[n * CH + (k - 128)];
    } else {
        if (k >= 128) v = W_hh[(n - 128) * CH + (k - 128)];
    }
    hi[i] = __float2bfloat16_rn(v);
    lo[i] = __float2bfloat16_rn(v - __bfloat162float(__float2bfloat16_rn(v)));
}

// ---------------- CSR build -------------------------------------------------
__global__ void hist_kernel(const int* __restrict__ sd, int* __restrict__ deg, int nE)
{
    int i = blockIdx.x * blockDim.x + threadIdx.x;
    if (i < nE) atomicAdd(&deg[sd[nE + i]], 1);
}

__global__ void scan1_kernel(const int* __restrict__ deg, int* __restrict__ pref,
                             int* __restrict__ bsum, int nN)
{
    __shared__ int sh[256];
    int base = blockIdx.x * 1024;
    int t = threadIdx.x;
    int v[4]; int s = 0;
    #pragma unroll
    for (int q = 0; q < 4; q++) {
        int idx = base + t * 4 + q;
        v[q] = (idx < nN) ? deg[idx] : 0;
        s += v[q];
    }
    sh[t] = s; __syncthreads();
    for (int o = 1; o < 256; o <<= 1) {
        int x = (t >= o) ? sh[t - o] : 0;
        __syncthreads();
        sh[t] += x;
        __syncthreads();
    }
    int run = sh[t] - s;
    #pragma unroll
    for (int q = 0; q < 4; q++) {
        int idx = base + t * 4 + q;
        if (idx < nN) pref[idx] = run;
        run += v[q];
    }
    if (t == 255) bsum[blockIdx.x] = sh[255];
}

__global__ void scan2_kernel(int* __restrict__ bsum, int nb)
{
    if (threadIdx.x == 0) {
        int acc = 0;
        for (int i = 0; i < nb; i++) { int v = bsum[i]; bsum[i] = acc; acc += v; }
    }
}

__global__ void scan3_kernel(int* __restrict__ pref, const int* __restrict__ bsum,
                             int* __restrict__ cur, int nN)
{
    int i = blockIdx.x * blockDim.x + threadIdx.x;
    if (i < nN) {
        int v = pref[i] + bsum[i >> 10];
        pref[i] = v;
        cur[i] = v;
    }
}

__global__ void fill_kernel(const int* __restrict__ sd, int* __restrict__ cur,
                            int* __restrict__ col, int nE)
{
    int i = blockIdx.x * blockDim.x + threadIdx.x;
    if (i < nE) {
        int d = sd[nE + i];
        int pos = atomicAdd(&cur[d], 1);
        col[pos] = sd[i];
    }
}

// ---------------- CSR aggregation: one warp per dst node -------------------
__global__ __launch_bounds__(256)
void aggregate_kernel(const int* __restrict__ pref, const int* __restrict__ deg,
                      const int* __restrict__ col, const float* __restrict__ h,
                      float* __restrict__ agg, int nN)
{
    int w = (blockIdx.x * blockDim.x + threadIdx.x) >> 5;
    int lane = threadIdx.x & 31;
    if (w >= nN) return;
    int st = pref[w], dg = deg[w];
    float4 a = make_float4(0.f, 0.f, 0.f, 0.f);
    for (int j = 0; j < dg; j++) {
        int s = col[st + j];
        float4 v = *reinterpret_cast<const float4*>(h + (size_t)s * CH + lane * 4);
        a.x += v.x; a.y += v.y; a.z += v.z; a.w += v.w;
    }
    *reinterpret_cast<float4*>(agg + (size_t)w * CH + lane * 4) = a;
}

// ---------------- bf16-split mma.sync GEMM ---------------------------------
//  D[M,Ntot](fp32) = A[M,K](fp32) @ B[K,N] via Ahi*Bhi + Ahi*Blo + Alo*Bhi
//  CTA tile 128x128, BK=32, 8 warps (4m x 2n), double-buffered.
#define PITCH 80
#define SA_HI(b) ((b) * 40960 + 0)
#define SA_LO(b) ((b) * 40960 + 10240)
#define SB_HI(b) ((b) * 40960 + 20480)
#define SB_LO(b) ((b) * 40960 + 30720)
#define GEMM_SMEM 81920

__global__ __launch_bounds__(256)
void gemm_mma(const float* __restrict__ A0, const float* __restrict__ A1, int K0, int lda,
              const __nv_bfloat16* __restrict__ Bhi, const __nv_bfloat16* __restrict__ Blo, int ldb,
              float* __restrict__ D, int M, int Ntot, int K, int gru)
{
    extern __shared__ char smem[];
    const uint32_t sb = smem_u32(smem);
    const int tid  = threadIdx.x;
    const int lane = tid & 31;
    const int wid  = tid >> 5;
    const int wm   = wid & 3;
    const int wn   = wid >> 2;
    const int bn   = blockIdx.x, bm = blockIdx.y;
    const int row0 = bm * 128, ncol0 = bn * 128;

    int ks = 0, ke = K;
    if (gru) { if (bn == 2) ke = 128; else if (bn == 3) ks = 128; }
    const int nkc = (ke - ks) >> 5;

    const int frow  = tid >> 1;
    const int fhalf = tid & 1;

    float4 sa[4];
    uint4  sbh[2], sbl[2];

    auto load_stage = [&](int kt) {
        const float* Ap; int kb;
        if (kt < K0) { Ap = A0; kb = kt; } else { Ap = A1; kb = kt - K0; }
        const float* asrc = Ap + (size_t)(row0 + frow) * lda + kb + fhalf * 16;
        if (row0 + frow < M) {
            sa[0] = *(const float4*)(asrc + 0);
            sa[1] = *(const float4*)(asrc + 4);
            sa[2] = *(const float4*)(asrc + 8);
            sa[3] = *(const float4*)(asrc + 12);
        } else {
            sa[0] = sa[1] = sa[2] = sa[3] = make_float4(0.f, 0.f, 0.f, 0.f);
        }
        const __nv_bfloat16* bh = Bhi + (size_t)(ncol0 + frow) * ldb + kt + fhalf * 16;
        const __nv_bfloat16* bl = Blo + (size_t)(ncol0 + frow) * ldb + kt + fhalf * 16;
        sbh[0] = *(const uint4*)(bh);     sbh[1] = *(const uint4*)(bh + 8);
        sbl[0] = *(const uint4*)(bl);     sbl[1] = *(const uint4*)(bl + 8);
    };

    auto store_stage = [&](int b) {
        char* ah = smem + SA_HI(b) + frow * PITCH + fhalf * 32;
        char* al = smem + SA_LO(b) + frow * PITCH + fhalf * 32;
        #pragma unroll
        for (int q = 0; q < 4; q++) {
            ushort4 oh, ol;
            oh.x = bfhi(sa[q].x); oh.y = bfhi(sa[q].y); oh.z = bfhi(sa[q].z); oh.w = bfhi(sa[q].w);
            ol.x = bflo(sa[q].x); ol.y = bflo(sa[q].y); ol.z = bflo(sa[q].z); ol.w = bflo(sa[q].w);
            *(ushort4*)(ah + q * 8) = oh;
            *(ushort4*)(al + q * 8) = ol;
        }
        char* bh = smem + SB_HI(b) + frow * PITCH + fhalf * 32;
        char* bl = smem + SB_LO(b) + frow * PITCH + fhalf * 32;
        *(uint4*)(bh)      = sbh[0];  *(uint4*)(bh + 16) = sbh[1];
        *(uint4*)(bl)      = sbl[0];  *(uint4*)(bl + 16) = sbl[1];
    };

    float acc[2][8][4];
    #pragma unroll
    for (int i = 0; i < 2; i++)
        #pragma unroll
        for (int j = 0; j < 8; j++)
            #pragma unroll
            for (int q = 0; q < 4; q++) acc[i][j][q] = 0.0f;

    const int lt = lane >> 3;
    const int lr = lane & 7;

    load_stage(ks);
    store_stage(0);
    __syncthreads();

    for (int c = 0; c < nkc; c++) {
        const int b = c & 1;
        const bool nxt = (c + 1) < nkc;
        if (nxt) load_stage(ks + (c + 1) * 32);

        #pragma unroll
        for (int c16 = 0; c16 < 2; c16++) {
            uint32_t ah[2][4], al[2][4], bhf[8][2], blf[8][2];
            #pragma unroll
            for (int mt = 0; mt < 2; mt++) {
                int mrow = wm * 32 + mt * 16 + ((lt & 1) << 3) + lr;
                uint32_t off = (uint32_t)(mrow * PITCH + c16 * 32 + ((lt >> 1) << 4));
                ldm4(ah[mt][0], ah[mt][1], ah[mt][2], ah[mt][3], sb + SA_HI(b) + off);
                ldm4(al[mt][0], al[mt][1], al[mt][2], al[mt][3], sb + SA_LO(b) + off);
            }
            #pragma unroll
            for (int np = 0; np < 4; np++) {
                int nrow = wn * 64 + np * 16 + ((lt >> 1) << 3) + lr;
                uint32_t off = (uint32_t)(nrow * PITCH + c16 * 32 + ((lt & 1) << 4));
                uint32_t r0, r1, r2, r3;
                ldm4(r0, r1, r2, r3, sb + SB_HI(b) + off);
                bhf[2 * np][0] = r0; bhf[2 * np][1] = r1;
                bhf[2 * np + 1][0] = r2; bhf[2 * np + 1][1] = r3;
                ldm4(r0, r1, r2, r3, sb + SB_LO(b) + off);
                blf[2 * np][0] = r0; blf[2 * np][1] = r1;
                blf[2 * np + 1][0] = r2; blf[2 * np + 1][1] = r3;
            }
            #pragma unroll
            for (int mt = 0; mt < 2; mt++)
                #pragma unroll
                for (int nt = 0; nt < 8; nt++) {
                    mma_bf16(acc[mt][nt], ah[mt], bhf[nt]);
                    mma_bf16(acc[mt][nt], ah[mt], blf[nt]);
                    mma_bf16(acc[mt][nt], al[mt], bhf[nt]);
                }
        }
        __syncthreads();
        if (nxt) { store_stage(b ^ 1); __syncthreads(); }
    }

    #pragma unroll
    for (int mt = 0; mt < 2; mt++)
        #pragma unroll
        for (int nt = 0; nt < 8; nt++) {
            int r_ = row0 + wm * 32 + mt * 16 + (lane >> 2);
            int cc = ncol0 + wn * 64 + nt * 8 + ((lane & 3) << 1);
            if (r_ < M)
                *(float2*)(D + (size_t)r_ * Ntot + cc) = make_float2(acc[mt][nt][0], acc[mt][nt][1]);
            if (r_ + 8 < M)
                *(float2*)(D + (size_t)(r_ + 8) * Ntot + cc) = make_float2(acc[mt][nt][2], acc[mt][nt][3]);
        }
}

// ---------------- GRU gate epilogue (float4 vectorized) --------------------
__global__ void gates_kernel(const float* __restrict__ G,
                             const float* __restrict__ b_ih,
                             const float* __restrict__ b_hh,
                             float* __restrict__ h, int nN)
{
    int idx = blockIdx.x * blockDim.x + threadIdx.x;
    if (idx >= nN * 32) return;
    int n  = idx >> 5;
    int c4 = (idx & 31) * 4;
    const float* g = G + (size_t)n * GW;
    float4 gr  = *(const float4*)(g + c4);
    float4 gz  = *(const float4*)(g + 128 + c4);
    float4 gin = *(const float4*)(g + 256 + c4);
    float4 ghn = *(const float4*)(g + 384 + c4);
    float4 bir = *(const float4*)(b_ih + c4);
    float4 bhr = *(const float4*)(b_hh + c4);
    float4 biz = *(const float4*)(b_ih + 128 + c4);
    float4 bhz = *(const float4*)(b_hh + 128 + c4);
    float4 bin = *(const float4*)(b_ih + 256 + c4);
    float4 bhn = *(const float4*)(b_hh + 256 + c4);
    float4 hv  = *(const float4*)(h + (size_t)n * CH + c4);
    float o[4];
    #pragma unroll
    for (int q = 0; q < 4; q++) {
        float grv  = ((const float*)&gr)[q]  + ((const float*)&bir)[q] + ((const float*)&bhr)[q];
        float gzv  = ((const float*)&gz)[q]  + ((const float*)&biz)[q] + ((const float*)&bhz)[q];
        float ginv = ((const float*)&gin)[q] + ((const float*)&bin)[q];
        float ghnv = ((const float*)&ghn)[q] + ((const float*)&bhn)[q];
        float r = 1.0f / (1.0f + expf(-grv));
        float z = 1.0f / (1.0f + expf(-gzv));
        float nn = tanhf(ginv + r * ghnv);
        float ho = ((const float*)&hv)[q];
        o[q] = (1.0f - z) * nn + z * ho;
    }
    *(float4*)(h + (size_t)n * CH + c4) = make_float4(o[0], o[1], o[2], o[3]);
}

// ---------------- readout --------------------------------------------------
__global__ void reduce_kernel(const float* __restrict__ h, float* __restrict__ gsum, int nN)
{
    int c = threadIdx.x;
    float acc = 0.0f;
    for (int n = blockIdx.x; n < nN; n += gridDim.x) {
        float v = h[(size_t)n * CH + c];
        v = (v >= 0.0f) ? v : 0.01f * v;
        acc += v;
    }
    atomicAdd(&gsum[c], acc);
}

__global__ void final_kernel(const float* __restrict__ gsum,
                             const float* __restrict__ W_pred,
                             const float* __restrict__ b_pred,
                             float* __restrict__ out, float invN)
{
    __shared__ float s[CH];
    int t = threadIdx.x;
    s[t] = gsum[t] * invN * W_pred[t];
    __syncthreads();
    #pragma unroll
    for (int o = 64; o > 0; o >>= 1) {
        if (t < o) s[t] += s[t + o];
        __syncthreads();
    }
    if (t == 0) out[0] = s[0] + b_pred[0];
}

// ---------------- launch ----------------------------------------------------
extern "C" void kernel_launch(void* const* d_in, const int* in_sizes, int n_in,
                              void* d_out, int out_size)
{
    const float*  x      = (const float*)d_in[0];
    const void*   ei     = d_in[1];
    const float*  W_in   = (const float*)d_in[2];
    const float*  W_mpnn = (const float*)d_in[3];
    const float*  W_ih   = (const float*)d_in[4];
    const float*  W_hh   = (const float*)d_in[5];
    const float*  b_ih   = (const float*)d_in[6];
    const float*  b_hh   = (const float*)d_in[7];
    const float*  W_pred = (const float*)d_in[8];
    const float*  b_pred = (const float*)d_in[9];
    float*        out    = (float*)d_out;
    (void)n_in; (void)out_size;

    const int nN = in_sizes[0] / FIN;      // 100000
    const int nE = in_sizes[1] / 2;        // 1600000

    float *p_h, *p_agg, *p_G, *p_gsum, *p_W2;
    int *p_sd, *p_flag, *p_deg, *p_pref, *p_cur, *p_col, *p_bsum;
    __nv_bfloat16 *p_beh, *p_bel, *p_bgh, *p_bgl;
    cudaGetSymbolAddress((void**)&p_h,    g_h);
    cudaGetSymbolAddress((void**)&p_agg,  g_agg);
    cudaGetSymbolAddress((void**)&p_G,    g_G);
    cudaGetSymbolAddress((void**)&p_gsum, g_gsum);
    cudaGetSymbolAddress((void**)&p_W2,   g_W2);
    cudaGetSymbolAddress((void**)&p_sd,   g_sd);
    cudaGetSymbolAddress((void**)&p_flag, g_idx64);
    cudaGetSymbolAddress((void**)&p_deg,  g_deg);
    cudaGetSymbolAddress((void**)&p_pref, g_pref);
    cudaGetSymbolAddress((void**)&p_cur,  g_cur);
    cudaGetSymbolAddress((void**)&p_col,  g_col);
    cudaGetSymbolAddress((void**)&p_bsum, g_bsum);
    cudaGetSymbolAddress((void**)&p_beh,  g_Bemb_hi);
    cudaGetSymbolAddress((void**)&p_bel,  g_Bemb_lo);
    cudaGetSymbolAddress((void**)&p_bgh,  g_Bgru_hi);
    cudaGetSymbolAddress((void**)&p_bgl,  g_Bgru_lo);

    cudaFuncSetAttribute(gemm_mma, cudaFuncAttributeMaxDynamicSharedMemorySize, GEMM_SMEM);

    const int mtiles = (nN + 127) / 128;
    const int nb = (nN + 1023) / 1024;

    // --- prep (ordered so the 6th kernel launch is the embed GEMM for ncu -s 5)
    detect_idx_kernel<<<1, 512>>>((const int*)ei, p_flag);                          // 1
    convert_idx_kernel<<<(2 * nE + 255) / 256, 256>>>(ei, p_sd, p_flag, 2 * nE);    // 2
    prep_bemb<<<(CH * FIN + 255) / 256, 256>>>(W_in, p_beh, p_bel);                 // 3
    prep_w2<<<(STEPS * CH * 384 + 255) / 256, 256>>>(W_mpnn, W_ih, p_W2);           // 4
    prep_bgru<<<(STEPS * GW * 256 + 255) / 256, 256>>>(p_W2, W_hh, p_bgh, p_bgl);   // 5

    // h = x @ W_in^T     [nN,64] x [64,128]                                        // 6
    gemm_mma<<<dim3(1, mtiles), 256, GEMM_SMEM>>>(
        x, x, FIN, FIN, p_beh, p_bel, FIN, p_h, nN, CH, FIN, 0);

    // --- CSR build
    cudaMemsetAsync(p_deg, 0, (size_t)nN * sizeof(int));
    hist_kernel<<<(nE + 255) / 256, 256>>>(p_sd, p_deg, nE);
    scan1_kernel<<<nb, 256>>>(p_deg, p_pref, p_bsum, nN);
    scan2_kernel<<<1, 32>>>(p_bsum, nb);
    scan3_kernel<<<(nN + 255) / 256, 256>>>(p_pref, p_bsum, p_cur, nN);
    fill_kernel<<<(nE + 255) / 256, 256>>>(p_sd, p_cur, p_col, nE);

    for (int i = 0; i < STEPS; i++) {
        // agg_h = CSR-aggregate(h[src] -> dst)   (W_mpnn folded into GRU weights)
        aggregate_kernel<<<(nN * 32 + 255) / 256, 256>>>(p_pref, p_deg, p_col, p_h, p_agg, nN);

        // G = [agg_h | h] @ Wcomb[i]   [nN,256] x [256,512], zero-blocks skipped
        gemm_mma<<<dim3(4, mtiles), 256, GEMM_SMEM>>>(
            p_agg, p_h, CH, CH,
            p_bgh + (size_t)i * GW * 256, p_bgl + (size_t)i * GW * 256, 256,
            p_G, nN, GW, 2 * CH, 1);

        // GRU gate update (in-place on h)
        gates_kernel<<<(nN * 32 + 255) / 256, 256>>>(p_G, b_ih, b_hh, p_h, nN);
    }

    // readout
    cudaMemsetAsync(p_gsum, 0, CH * sizeof(float));
    reduce_kernel<<<2048, CH>>>(p_h, p_gsum, nN);
    final_kernel<<<1, CH>>>(p_gsum, W_pred, b_pred, out, 1.0f / (float)nN);
}